// round 1
// baseline (speedup 1.0000x reference)
#include <cuda_runtime.h>
#include <math.h>

#define S 1024
#define D 768
#define LAYERS 12
#define HEADS 24
#define DKV 32
#define QKV_N 2304
#define FF_N 1536
#define VSZ 50304
#define NCH 32   // number of sequence chunks
#define CT 32    // tokens per chunk

// ---------------- scratch (static device allocations; no cudaMalloc) -------
__device__ float g_x[S*D];
__device__ float g_xn[S*D];
__device__ float g_h[S*2*D];
__device__ float g_qkv[S*QKV_N];
__device__ float g_att[S*D];
__device__ float g_ff1[S*FF_N];
__device__ float g_glu[S*D];
__device__ float g_Asum[HEADS*NCH*DKV*DKV];
__device__ float g_Zsum[HEADS*NCH*DKV];
__device__ float g_Mcar[HEADS*NCH*DKV*DKV];
__device__ float g_Zcar[HEADS*NCH*DKV];

// ---------------- embedding gather -----------------------------------------
__global__ void embed_k(const int* __restrict__ tok, const float* __restrict__ ew,
                        float* __restrict__ x) {
    int s = blockIdx.x;
    int t = tok[s];
    for (int d = threadIdx.x; d < D; d += blockDim.x)
        x[(size_t)s*D + d] = ew[(size_t)t*D + d];
}

// ---------------- SGEMM: C = A(MxK) @ B  (+bias +res) -----------------------
// BT=false: B is KxN row-major.  BT=true: B is NxK row-major (C = A @ B^T).
// 64x64 tile, BK=16, 256 threads, 4x4 microtile (strided fragments).
template<bool BT>
__global__ __launch_bounds__(256) void gemm_k(
    const float* __restrict__ A, const float* __restrict__ B,
    const float* __restrict__ bias, const float* __restrict__ res,
    float* __restrict__ C, int M, int N, int K)
{
    __shared__ float As[16][65];
    __shared__ float Bs[16][65];
    const int tid = threadIdx.x;
    const int tx = tid & 15, ty = tid >> 4;
    const int m0 = blockIdx.y * 64, n0 = blockIdx.x * 64;
    const int r  = tid >> 2, kq = (tid & 3) * 4;

    float acc[4][4] = {};

    for (int k0 = 0; k0 < K; k0 += 16) {
        // A tile: 64 rows x 16 k
        float4 av = *(const float4*)&A[(size_t)(m0 + r) * K + k0 + kq];
        As[kq+0][r] = av.x; As[kq+1][r] = av.y; As[kq+2][r] = av.z; As[kq+3][r] = av.w;
        if (BT) {
            float4 bv = *(const float4*)&B[(size_t)(n0 + r) * K + k0 + kq];
            Bs[kq+0][r] = bv.x; Bs[kq+1][r] = bv.y; Bs[kq+2][r] = bv.z; Bs[kq+3][r] = bv.w;
        } else {
            int kk = tid >> 4, c4 = (tid & 15) * 4;
            float4 bv = *(const float4*)&B[(size_t)(k0 + kk) * N + n0 + c4];
            Bs[kk][c4+0] = bv.x; Bs[kk][c4+1] = bv.y; Bs[kk][c4+2] = bv.z; Bs[kk][c4+3] = bv.w;
        }
        __syncthreads();
        #pragma unroll
        for (int kk = 0; kk < 16; kk++) {
            float a[4], b[4];
            #pragma unroll
            for (int i = 0; i < 4; i++) a[i] = As[kk][ty + 16*i];
            #pragma unroll
            for (int j = 0; j < 4; j++) b[j] = Bs[kk][tx + 16*j];
            #pragma unroll
            for (int i = 0; i < 4; i++)
                #pragma unroll
                for (int j = 0; j < 4; j++)
                    acc[i][j] = fmaf(a[i], b[j], acc[i][j]);
        }
        __syncthreads();
    }
    #pragma unroll
    for (int i = 0; i < 4; i++) {
        int m = m0 + ty + 16*i;
        #pragma unroll
        for (int j = 0; j < 4; j++) {
            int n = n0 + tx + 16*j;
            float v = acc[i][j];
            if (bias) v += bias[n];
            if (res)  v += res[(size_t)m * N + n];
            C[(size_t)m * N + n] = v;
        }
    }
}

// ---------------- layernorm (one row per block, 256 threads) ----------------
__global__ __launch_bounds__(256) void ln_k(const float* __restrict__ x,
    const float* __restrict__ g, const float* __restrict__ b, float* __restrict__ y)
{
    __shared__ float sh[8];
    int s = blockIdx.x;
    int tid = threadIdx.x;
    const float* row = x + (size_t)s * D;
    float v0 = row[tid], v1 = row[tid+256], v2 = row[tid+512];
    float sum = v0 + v1 + v2;
    #pragma unroll
    for (int o = 16; o > 0; o >>= 1) sum += __shfl_xor_sync(0xffffffffu, sum, o);
    if ((tid & 31) == 0) sh[tid >> 5] = sum;
    __syncthreads();
    float tot = sh[0]+sh[1]+sh[2]+sh[3]+sh[4]+sh[5]+sh[6]+sh[7];
    float mean = tot * (1.0f/768.0f);
    float d0 = v0 - mean, d1 = v1 - mean, d2 = v2 - mean;
    float vs = d0*d0 + d1*d1 + d2*d2;
    #pragma unroll
    for (int o = 16; o > 0; o >>= 1) vs += __shfl_xor_sync(0xffffffffu, vs, o);
    __syncthreads();
    if ((tid & 31) == 0) sh[tid >> 5] = vs;
    __syncthreads();
    float var = (sh[0]+sh[1]+sh[2]+sh[3]+sh[4]+sh[5]+sh[6]+sh[7]) * (1.0f/768.0f);
    float inv = rsqrtf(var + 1e-5f);
    y[(size_t)s*D + tid      ] = d0*inv*g[tid      ] + b[tid      ];
    y[(size_t)s*D + tid + 256] = d1*inv*g[tid + 256] + b[tid + 256];
    y[(size_t)s*D + tid + 512] = d2*inv*g[tid + 512] + b[tid + 512];
}

// ---------------- minGRU-style position scan (per-channel serial) -----------
// h: (S, 2D). log_coeffs = log_sigmoid(h[:, :D]); logits = h[:, D:].
// a*[t] = prefix sum of log_coeffs, rec[t] = a*[t] + logcumsumexp(logits - a*).
__global__ void posscan_k(const float* __restrict__ h, float* __restrict__ x) {
    int d = blockIdx.x * 256 + threadIdx.x;
    if (d >= D) return;
    float acc = 0.0f;   // a_star (inclusive)
    float c   = 0.0f;   // running logcumsumexp (term for t=0 is exactly 0)
    for (int s = 0; s < S; s++) {
        float hv = h[(size_t)s*(2*D) + d];
        float lg = h[(size_t)s*(2*D) + D + d];
        float lc = (hv >= 0.0f) ? (-log1pf(expf(-hv))) : (hv - log1pf(expf(hv)));
        acc += lc;
        float t = lg - acc;
        float mx = fmaxf(c, t), mn = fminf(c, t);
        c = mx + log1pf(expf(mn - mx));
        x[(size_t)s*D + d] += acc + c;
    }
}

// ---------------- attention pass A: per-chunk sums  EK^T@EV, colsum(EK) -----
__global__ __launch_bounds__(1024) void attnA_k(const float* __restrict__ qkv,
    float* __restrict__ Asum, float* __restrict__ Zsum)
{
    int c = blockIdx.x, hh = blockIdx.y;
    int tid = threadIdx.x, lane = tid & 31, wid = tid >> 5;
    __shared__ float ek[CT][33], ev[CT][33];
    const float* base = qkv + (size_t)(c*CT + wid)*QKV_N + hh*96;
    ek[wid][lane] = expf(base[32 + lane]);
    ev[wid][lane] = expf(base[64 + lane]);
    __syncthreads();
    // thread = (k=wid, v=lane)
    float m = 0.0f;
    #pragma unroll
    for (int t = 0; t < CT; t++) m = fmaf(ek[t][wid], ev[t][lane], m);
    Asum[(size_t)(((hh*NCH)+c)*DKV + wid)*DKV + lane] = m;
    if (wid == 0) {
        float z = 0.0f;
        #pragma unroll
        for (int t = 0; t < CT; t++) z += ek[t][lane];
        Zsum[(size_t)((hh*NCH)+c)*DKV + lane] = z;
    }
}

// ---------------- attention pass B: exclusive prefix over chunks ------------
__global__ __launch_bounds__(1024) void attnB_k(const float* __restrict__ Asum,
    const float* __restrict__ Zsum, float* __restrict__ Mcar, float* __restrict__ Zcar)
{
    int hh = blockIdx.x;
    int tid = threadIdx.x, lane = tid & 31, wid = tid >> 5;
    float run = 0.0f;
    for (int c = 0; c < NCH; c++) {
        size_t idx = (size_t)(((hh*NCH)+c)*DKV + wid)*DKV + lane;
        Mcar[idx] = run;
        run += Asum[idx];
    }
    if (wid == 0) {
        float rz = 0.0f;
        for (int c = 0; c < NCH; c++) {
            size_t iz = (size_t)((hh*NCH)+c)*DKV + lane;
            Zcar[iz] = rz;
            rz += Zsum[iz];
        }
    }
}

// ---------------- attention pass C: intra-chunk + carry, write att ----------
__global__ __launch_bounds__(1024) void attnC_k(const float* __restrict__ qkv,
    const float* __restrict__ Mcar, const float* __restrict__ Zcar,
    float* __restrict__ att)
{
    int c = blockIdx.x, hh = blockIdx.y;
    int tid = threadIdx.x, lane = tid & 31, wid = tid >> 5;
    __shared__ float eq[CT][33], ek[CT][33], ev[CT][33], P[CT][33], M0[DKV][33];
    __shared__ float z0[DKV];
    const float* base = qkv + (size_t)(c*CT + wid)*QKV_N + hh*96;
    eq[wid][lane] = expf(base[      lane]);
    ek[wid][lane] = expf(base[32 +  lane]);
    ev[wid][lane] = expf(base[64 +  lane]);
    M0[wid][lane] = Mcar[(size_t)(((hh*NCH)+c)*DKV + wid)*DKV + lane];
    if (tid < DKV) z0[tid] = Zcar[(size_t)((hh*NCH)+c)*DKV + tid];
    __syncthreads();
    // P[t=wid][s=lane] = eq_t . ek_s
    float p = 0.0f;
    #pragma unroll
    for (int k = 0; k < DKV; k++) p = fmaf(eq[wid][k], ek[lane][k], p);
    P[wid][lane] = p;
    __syncthreads();
    // thread = (t=wid, v=lane)
    float num = 0.0f, den = 0.0f;
    #pragma unroll
    for (int k = 0; k < DKV; k++) {
        float q = eq[wid][k];
        num = fmaf(q, M0[k][lane], num);
        den = fmaf(q, z0[k], den);
    }
    for (int s2 = 0; s2 <= wid; s2++) {   // inclusive causal mask
        float ps = P[wid][s2];
        num = fmaf(ps, ev[s2][lane], num);
        den += ps;
    }
    att[(size_t)(c*CT + wid)*D + hh*DKV + lane] = logf(num) - logf(den);
}

// ---------------- GLU: o = z[:, :D] * sigmoid(z[:, D:]) ---------------------
__global__ void glu_k(const float* __restrict__ z, float* __restrict__ o) {
    int i = blockIdx.x*256 + threadIdx.x;
    int s = i / D, d = i - s*D;
    float a = z[(size_t)s*FF_N + d];
    float g = z[(size_t)s*FF_N + D + d];
    o[i] = a * (1.0f / (1.0f + expf(-g)));
}

// ---------------- launcher ---------------------------------------------------
extern "C" void kernel_launch(void* const* d_in, const int* in_sizes, int n_in,
                              void* d_out, int out_size)
{
    const int*   tok  = (const int*)  d_in[0];
    const float* embw = (const float*)d_in[1];
    const float* posw = (const float*)d_in[2];
    const float* posb = (const float*)d_in[3];
    const float* ln1g = (const float*)d_in[4];
    const float* ln1b = (const float*)d_in[5];
    const float* qkvw = (const float*)d_in[6];
    const float* qkvb = (const float*)d_in[7];
    const float* ffw1 = (const float*)d_in[8];
    const float* ffb1 = (const float*)d_in[9];
    const float* ffw2 = (const float*)d_in[10];
    const float* lnfg = (const float*)d_in[11];
    const float* lnfb = (const float*)d_in[12];
    float* out = (float*)d_out;

    float *x,*xn,*hh,*qkv,*att,*ff1,*glub,*Asum,*Zsum,*Mcar,*Zcar;
    cudaGetSymbolAddress((void**)&x,    g_x);
    cudaGetSymbolAddress((void**)&xn,   g_xn);
    cudaGetSymbolAddress((void**)&hh,   g_h);
    cudaGetSymbolAddress((void**)&qkv,  g_qkv);
    cudaGetSymbolAddress((void**)&att,  g_att);
    cudaGetSymbolAddress((void**)&ff1,  g_ff1);
    cudaGetSymbolAddress((void**)&glub, g_glu);
    cudaGetSymbolAddress((void**)&Asum, g_Asum);
    cudaGetSymbolAddress((void**)&Zsum, g_Zsum);
    cudaGetSymbolAddress((void**)&Mcar, g_Mcar);
    cudaGetSymbolAddress((void**)&Zcar, g_Zcar);

    // embed + position recurrence
    embed_k<<<S, 256>>>(tok, embw, x);
    gemm_k<false><<<dim3((2*D)/64, S/64), 256>>>(x, posw, posb, nullptr, hh, S, 2*D, D);
    posscan_k<<<3, 256>>>(hh, x);

    for (int l = 0; l < LAYERS; l++) {
        ln_k<<<S, 256>>>(x, ln1g + (size_t)l*D, ln1b + (size_t)l*D, xn);
        gemm_k<false><<<dim3(QKV_N/64, S/64), 256>>>(
            xn, qkvw + (size_t)l*D*QKV_N, qkvb + (size_t)l*QKV_N, nullptr, qkv, S, QKV_N, D);
        attnA_k<<<dim3(NCH, HEADS), 1024>>>(qkv, Asum, Zsum);
        attnB_k<<<HEADS, 1024>>>(Asum, Zsum, Mcar, Zcar);
        attnC_k<<<dim3(NCH, HEADS), 1024>>>(qkv, Mcar, Zcar, att);
        gemm_k<false><<<dim3(FF_N/64, S/64), 256>>>(
            att, ffw1 + (size_t)l*D*FF_N, ffb1 + (size_t)l*FF_N, nullptr, ff1, S, FF_N, D);
        glu_k<<<(S*D)/256, 256>>>(ff1, glub);
        gemm_k<false><<<dim3(D/64, S/64), 256>>>(
            glub, ffw2 + (size_t)l*D*D, nullptr, x, x, S, D, D);
    }

    ln_k<<<S, 256>>>(x, lnfg, lnfb, xn);
    gemm_k<true><<<dim3(VSZ/64, S/64), 256>>>(xn, embw, nullptr, nullptr, out, S, VSZ, D);
}

// round 2
// speedup vs baseline: 1.3535x; 1.3535x over previous
#include <cuda_runtime.h>
#include <math.h>

#define S 1024
#define D 768
#define LAYERS 12
#define HEADS 24
#define DKV 32
#define QKV_N 2304
#define FF_N 1536
#define VSZ 50304
#define NCH 32
#define CT 32

// ---------------- scratch -----------------------------------------------
__device__ float g_x[S*D];
__device__ float g_xn[S*D];
__device__ float g_h[S*2*D];
__device__ float g_qkv[S*QKV_N];
__device__ float g_att[S*D];
__device__ float g_ff1[S*FF_N];
__device__ float g_glu[S*D];
__device__ float g_Asum[HEADS*NCH*DKV*DKV];
__device__ float g_Zsum[HEADS*NCH*DKV];
__device__ float g_Mcar[HEADS*NCH*DKV*DKV];
__device__ float g_Zcar[HEADS*NCH*DKV];

// ---------------- embedding gather --------------------------------------
__global__ void embed_k(const int* __restrict__ tok, const float* __restrict__ ew,
                        float* __restrict__ x) {
    int s = blockIdx.x;
    int t = tok[s];
    for (int d = threadIdx.x; d < D; d += blockDim.x)
        x[(size_t)s*D + d] = ew[(size_t)t*D + d];
}

// ---------------- tf32 helpers ------------------------------------------
__device__ __forceinline__ float f2tf(float x) {
    unsigned r;
    asm("cvt.rna.tf32.f32 %0, %1;" : "=r"(r) : "f"(x));
    return __uint_as_float(r);
}
__device__ __forceinline__ void mma8(float* c, const unsigned* a, const unsigned* b) {
    asm volatile(
        "mma.sync.aligned.m16n8k8.row.col.f32.tf32.tf32.f32 "
        "{%0,%1,%2,%3},{%4,%5,%6,%7},{%8,%9},{%0,%1,%2,%3};"
        : "+f"(c[0]), "+f"(c[1]), "+f"(c[2]), "+f"(c[3])
        : "r"(a[0]), "r"(a[1]), "r"(a[2]), "r"(a[3]), "r"(b[0]), "r"(b[1]));
}

// ---------------- tf32 tensor-core GEMM ----------------------------------
// C(MxN) = A(MxK) @ B (+bias +res).  BT=false: B is KxN. BT=true: B is NxK.
// 128x128 CTA tile, BK=32, 256 threads, warps 4x2 (warp tile 32x64).
// Requires M%128==0, N%128==0, K%32==0 (true for every call site).
#define BMT 128
#define BNT 128
#define BKT 32
#define LDT 132   // smem row stride (floats): stride%32==4 -> <=2-way frag conflicts

template<bool BT>
__global__ __launch_bounds__(256) void gemm_tc(
    const float* __restrict__ A, const float* __restrict__ B,
    const float* __restrict__ bias, const float* __restrict__ res,
    float* __restrict__ C, int M, int N, int K)
{
    __shared__ float As[BKT][LDT];   // As[k][m], tf32-rounded
    __shared__ float Bs[BKT][LDT];   // Bs[k][n], tf32-rounded

    const int tid  = threadIdx.x;
    const int wid  = tid >> 5, lane = tid & 31;
    const int g    = lane >> 2, tg = lane & 3;
    const int m0   = blockIdx.y * BMT, n0 = blockIdx.x * BNT;
    const int m0w  = (wid >> 1) * 32;   // warp row offset
    const int n0w  = (wid & 1) * 64;    // warp col offset

    float acc[2][8][4] = {};

    // staging indices
    const int la_m  = 0; (void)la_m;
    float4 ar[4], br[4];

    // ---- helpers as lambdas (inlined) ----
    auto loadA = [&](int k0) {
        #pragma unroll
        for (int j = 0; j < 4; j++) {
            int lin = tid + 256*j;
            int m = lin >> 3, kq = (lin & 7) * 4;
            ar[j] = *(const float4*)&A[(size_t)(m0 + m) * K + k0 + kq];
        }
    };
    auto loadB = [&](int k0) {
        #pragma unroll
        for (int j = 0; j < 4; j++) {
            int lin = tid + 256*j;
            if (BT) {
                int n = lin >> 3, kq = (lin & 7) * 4;
                br[j] = *(const float4*)&B[(size_t)(n0 + n) * K + k0 + kq];
            } else {
                int kk = lin >> 5, n4 = (lin & 31) * 4;
                br[j] = *(const float4*)&B[(size_t)(k0 + kk) * N + n0 + n4];
            }
        }
    };
    auto commit = [&]() {
        #pragma unroll
        for (int j = 0; j < 4; j++) {
            int lin = tid + 256*j;
            int m = lin >> 3, kq = (lin & 7) * 4;
            As[kq+0][m] = f2tf(ar[j].x); As[kq+1][m] = f2tf(ar[j].y);
            As[kq+2][m] = f2tf(ar[j].z); As[kq+3][m] = f2tf(ar[j].w);
        }
        #pragma unroll
        for (int j = 0; j < 4; j++) {
            int lin = tid + 256*j;
            if (BT) {
                int n = lin >> 3, kq = (lin & 7) * 4;
                Bs[kq+0][n] = f2tf(br[j].x); Bs[kq+1][n] = f2tf(br[j].y);
                Bs[kq+2][n] = f2tf(br[j].z); Bs[kq+3][n] = f2tf(br[j].w);
            } else {
                int kk = lin >> 5, n4 = (lin & 31) * 4;
                float4 v;
                v.x = f2tf(br[j].x); v.y = f2tf(br[j].y);
                v.z = f2tf(br[j].z); v.w = f2tf(br[j].w);
                *(float4*)&Bs[kk][n4] = v;
            }
        }
    };
    auto compute = [&]() {
        #pragma unroll
        for (int ks = 0; ks < 4; ks++) {
            const int kk = ks * 8;
            unsigned a[2][4], b[8][2];
            #pragma unroll
            for (int i = 0; i < 2; i++) {
                int m = m0w + i*16 + g;
                a[i][0] = __float_as_uint(As[kk+tg  ][m  ]);
                a[i][1] = __float_as_uint(As[kk+tg  ][m+8]);
                a[i][2] = __float_as_uint(As[kk+tg+4][m  ]);
                a[i][3] = __float_as_uint(As[kk+tg+4][m+8]);
            }
            #pragma unroll
            for (int j = 0; j < 8; j++) {
                int n = n0w + j*8 + g;
                b[j][0] = __float_as_uint(Bs[kk+tg  ][n]);
                b[j][1] = __float_as_uint(Bs[kk+tg+4][n]);
            }
            #pragma unroll
            for (int i = 0; i < 2; i++)
                #pragma unroll
                for (int j = 0; j < 8; j++)
                    mma8(acc[i][j], a[i], b[j]);
        }
    };

    // ---- pipeline ----
    loadA(0); loadB(0);
    commit();
    __syncthreads();
    const int NIT = K / BKT;
    for (int t = 1; t < NIT; t++) {
        loadA(t*BKT); loadB(t*BKT);
        compute();
        __syncthreads();
        commit();
        __syncthreads();
    }
    compute();

    // ---- epilogue ----
    #pragma unroll
    for (int i = 0; i < 2; i++) {
        int mA = m0 + m0w + i*16 + g;
        #pragma unroll
        for (int j = 0; j < 8; j++) {
            int col = n0 + n0w + j*8 + 2*tg;
            float b0 = bias ? bias[col] : 0.0f, b1 = bias ? bias[col+1] : 0.0f;
            float v0 = acc[i][j][0] + b0, v1 = acc[i][j][1] + b1;
            float v2 = acc[i][j][2] + b0, v3 = acc[i][j][3] + b1;
            if (res) {
                v0 += res[(size_t)mA*N + col];     v1 += res[(size_t)mA*N + col+1];
                v2 += res[(size_t)(mA+8)*N + col]; v3 += res[(size_t)(mA+8)*N + col+1];
            }
            *(float2*)&C[(size_t)mA*N + col]     = make_float2(v0, v1);
            *(float2*)&C[(size_t)(mA+8)*N + col] = make_float2(v2, v3);
        }
    }
}

// ---------------- layernorm ----------------------------------------------
__global__ __launch_bounds__(256) void ln_k(const float* __restrict__ x,
    const float* __restrict__ g, const float* __restrict__ b, float* __restrict__ y)
{
    __shared__ float sh[8];
    int s = blockIdx.x;
    int tid = threadIdx.x;
    const float* row = x + (size_t)s * D;
    float v0 = row[tid], v1 = row[tid+256], v2 = row[tid+512];
    float sum = v0 + v1 + v2;
    #pragma unroll
    for (int o = 16; o > 0; o >>= 1) sum += __shfl_xor_sync(0xffffffffu, sum, o);
    if ((tid & 31) == 0) sh[tid >> 5] = sum;
    __syncthreads();
    float tot = sh[0]+sh[1]+sh[2]+sh[3]+sh[4]+sh[5]+sh[6]+sh[7];
    float mean = tot * (1.0f/768.0f);
    float d0 = v0 - mean, d1 = v1 - mean, d2 = v2 - mean;
    float vs = d0*d0 + d1*d1 + d2*d2;
    #pragma unroll
    for (int o = 16; o > 0; o >>= 1) vs += __shfl_xor_sync(0xffffffffu, vs, o);
    __syncthreads();
    if ((tid & 31) == 0) sh[tid >> 5] = vs;
    __syncthreads();
    float var = (sh[0]+sh[1]+sh[2]+sh[3]+sh[4]+sh[5]+sh[6]+sh[7]) * (1.0f/768.0f);
    float inv = rsqrtf(var + 1e-5f);
    y[(size_t)s*D + tid      ] = d0*inv*g[tid      ] + b[tid      ];
    y[(size_t)s*D + tid + 256] = d1*inv*g[tid + 256] + b[tid + 256];
    y[(size_t)s*D + tid + 512] = d2*inv*g[tid + 512] + b[tid + 512];
}

// ---------------- position scan ------------------------------------------
__global__ void posscan_k(const float* __restrict__ h, float* __restrict__ x) {
    int d = blockIdx.x * 256 + threadIdx.x;
    if (d >= D) return;
    float acc = 0.0f;
    float c   = 0.0f;
    for (int s = 0; s < S; s++) {
        float hv = h[(size_t)s*(2*D) + d];
        float lg = h[(size_t)s*(2*D) + D + d];
        float lc = (hv >= 0.0f) ? (-log1pf(expf(-hv))) : (hv - log1pf(expf(hv)));
        acc += lc;
        float t = lg - acc;
        float mx = fmaxf(c, t), mn = fminf(c, t);
        c = mx + log1pf(expf(mn - mx));
        x[(size_t)s*D + d] += acc + c;
    }
}

// ---------------- attention pass A ---------------------------------------
__global__ __launch_bounds__(1024) void attnA_k(const float* __restrict__ qkv,
    float* __restrict__ Asum, float* __restrict__ Zsum)
{
    int c = blockIdx.x, hh = blockIdx.y;
    int tid = threadIdx.x, lane = tid & 31, wid = tid >> 5;
    __shared__ float ek[CT][33], ev[CT][33];
    const float* base = qkv + (size_t)(c*CT + wid)*QKV_N + hh*96;
    ek[wid][lane] = expf(base[32 + lane]);
    ev[wid][lane] = expf(base[64 + lane]);
    __syncthreads();
    float m = 0.0f;
    #pragma unroll
    for (int t = 0; t < CT; t++) m = fmaf(ek[t][wid], ev[t][lane], m);
    Asum[(size_t)(((hh*NCH)+c)*DKV + wid)*DKV + lane] = m;
    if (wid == 0) {
        float z = 0.0f;
        #pragma unroll
        for (int t = 0; t < CT; t++) z += ek[t][lane];
        Zsum[(size_t)((hh*NCH)+c)*DKV + lane] = z;
    }
}

// ---------------- attention pass B ---------------------------------------
__global__ __launch_bounds__(1024) void attnB_k(const float* __restrict__ Asum,
    const float* __restrict__ Zsum, float* __restrict__ Mcar, float* __restrict__ Zcar)
{
    int hh = blockIdx.x;
    int tid = threadIdx.x, lane = tid & 31, wid = tid >> 5;
    float run = 0.0f;
    for (int c = 0; c < NCH; c++) {
        size_t idx = (size_t)(((hh*NCH)+c)*DKV + wid)*DKV + lane;
        Mcar[idx] = run;
        run += Asum[idx];
    }
    if (wid == 0) {
        float rz = 0.0f;
        for (int c = 0; c < NCH; c++) {
            size_t iz = (size_t)((hh*NCH)+c)*DKV + lane;
            Zcar[iz] = rz;
            rz += Zsum[iz];
        }
    }
}

// ---------------- attention pass C ---------------------------------------
__global__ __launch_bounds__(1024) void attnC_k(const float* __restrict__ qkv,
    const float* __restrict__ Mcar, const float* __restrict__ Zcar,
    float* __restrict__ att)
{
    int c = blockIdx.x, hh = blockIdx.y;
    int tid = threadIdx.x, lane = tid & 31, wid = tid >> 5;
    __shared__ float eq[CT][33], ek[CT][33], ev[CT][33], P[CT][33], M0[DKV][33];
    __shared__ float z0[DKV];
    const float* base = qkv + (size_t)(c*CT + wid)*QKV_N + hh*96;
    eq[wid][lane] = expf(base[      lane]);
    ek[wid][lane] = expf(base[32 +  lane]);
    ev[wid][lane] = expf(base[64 +  lane]);
    M0[wid][lane] = Mcar[(size_t)(((hh*NCH)+c)*DKV + wid)*DKV + lane];
    if (tid < DKV) z0[tid] = Zcar[(size_t)((hh*NCH)+c)*DKV + tid];
    __syncthreads();
    float p = 0.0f;
    #pragma unroll
    for (int k = 0; k < DKV; k++) p = fmaf(eq[wid][k], ek[lane][k], p);
    P[wid][lane] = p;
    __syncthreads();
    float num = 0.0f, den = 0.0f;
    #pragma unroll
    for (int k = 0; k < DKV; k++) {
        float q = eq[wid][k];
        num = fmaf(q, M0[k][lane], num);
        den = fmaf(q, z0[k], den);
    }
    for (int s2 = 0; s2 <= wid; s2++) {
        float ps = P[wid][s2];
        num = fmaf(ps, ev[s2][lane], num);
        den += ps;
    }
    att[(size_t)(c*CT + wid)*D + hh*DKV + lane] = logf(num) - logf(den);
}

// ---------------- GLU ----------------------------------------------------
__global__ void glu_k(const float* __restrict__ z, float* __restrict__ o) {
    int i = blockIdx.x*256 + threadIdx.x;
    int s = i / D, d = i - s*D;
    float a = z[(size_t)s*FF_N + d];
    float g = z[(size_t)s*FF_N + D + d];
    o[i] = a * (1.0f / (1.0f + expf(-g)));
}

// ---------------- launcher -----------------------------------------------
extern "C" void kernel_launch(void* const* d_in, const int* in_sizes, int n_in,
                              void* d_out, int out_size)
{
    const int*   tok  = (const int*)  d_in[0];
    const float* embw = (const float*)d_in[1];
    const float* posw = (const float*)d_in[2];
    const float* posb = (const float*)d_in[3];
    const float* ln1g = (const float*)d_in[4];
    const float* ln1b = (const float*)d_in[5];
    const float* qkvw = (const float*)d_in[6];
    const float* qkvb = (const float*)d_in[7];
    const float* ffw1 = (const float*)d_in[8];
    const float* ffb1 = (const float*)d_in[9];
    const float* ffw2 = (const float*)d_in[10];
    const float* lnfg = (const float*)d_in[11];
    const float* lnfb = (const float*)d_in[12];
    float* out = (float*)d_out;

    float *x,*xn,*hh,*qkv,*att,*ff1,*glub,*Asum,*Zsum,*Mcar,*Zcar;
    cudaGetSymbolAddress((void**)&x,    g_x);
    cudaGetSymbolAddress((void**)&xn,   g_xn);
    cudaGetSymbolAddress((void**)&hh,   g_h);
    cudaGetSymbolAddress((void**)&qkv,  g_qkv);
    cudaGetSymbolAddress((void**)&att,  g_att);
    cudaGetSymbolAddress((void**)&ff1,  g_ff1);
    cudaGetSymbolAddress((void**)&glub, g_glu);
    cudaGetSymbolAddress((void**)&Asum, g_Asum);
    cudaGetSymbolAddress((void**)&Zsum, g_Zsum);
    cudaGetSymbolAddress((void**)&Mcar, g_Mcar);
    cudaGetSymbolAddress((void**)&Zcar, g_Zcar);

    embed_k<<<S, 256>>>(tok, embw, x);
    gemm_tc<false><<<dim3((2*D)/BNT, S/BMT), 256>>>(x, posw, posb, nullptr, hh, S, 2*D, D);
    posscan_k<<<3, 256>>>(hh, x);

    for (int l = 0; l < LAYERS; l++) {
        ln_k<<<S, 256>>>(x, ln1g + (size_t)l*D, ln1b + (size_t)l*D, xn);
        gemm_tc<false><<<dim3(QKV_N/BNT, S/BMT), 256>>>(
            xn, qkvw + (size_t)l*D*QKV_N, qkvb + (size_t)l*QKV_N, nullptr, qkv, S, QKV_N, D);
        attnA_k<<<dim3(NCH, HEADS), 1024>>>(qkv, Asum, Zsum);
        attnB_k<<<HEADS, 1024>>>(Asum, Zsum, Mcar, Zcar);
        attnC_k<<<dim3(NCH, HEADS), 1024>>>(qkv, Mcar, Zcar, att);
        gemm_tc<false><<<dim3(FF_N/BNT, S/BMT), 256>>>(
            att, ffw1 + (size_t)l*D*FF_N, ffb1 + (size_t)l*FF_N, nullptr, ff1, S, FF_N, D);
        glu_k<<<(S*D)/256, 256>>>(ff1, glub);
        gemm_tc<false><<<dim3(D/BNT, S/BMT), 256>>>(
            glub, ffw2 + (size_t)l*D*D, nullptr, x, x, S, D, D);
    }

    ln_k<<<S, 256>>>(x, lnfg, lnfb, xn);
    gemm_tc<true><<<dim3(VSZ/BNT, S/BMT), 256>>>(xn, embw, nullptr, nullptr, out, S, VSZ, D);
}

// round 4
// speedup vs baseline: 2.4896x; 1.8393x over previous
#include <cuda_runtime.h>
#include <math.h>

#define S 1024
#define D 768
#define LAYERS 12
#define HEADS 24
#define DKV 32
#define QKV_N 2304
#define FF_N 1536
#define VSZ 50304
#define NCH 32
#define CT 32

// ---------------- scratch -----------------------------------------------
__device__ float g_x[S*D];
__device__ float g_xn[S*D];
__device__ float g_h[S*2*D];
__device__ float g_qkv[S*QKV_N];
__device__ float g_att[S*D];
__device__ float g_ff1[S*FF_N];
__device__ float g_glu[S*D];
__device__ float g_Asum[HEADS*NCH*DKV*DKV];
__device__ float g_Zsum[HEADS*NCH*DKV];
__device__ float g_Mcar[HEADS*NCH*DKV*DKV];
__device__ float g_Zcar[HEADS*NCH*DKV];

// ---------------- embedding gather --------------------------------------
__global__ void embed_k(const int* __restrict__ tok, const float* __restrict__ ew,
                        float* __restrict__ x) {
    int s = blockIdx.x;
    int t = tok[s];
    for (int d = threadIdx.x; d < D; d += blockDim.x)
        x[(size_t)s*D + d] = ew[(size_t)t*D + d];
}

// ---------------- async-copy + tf32 helpers ------------------------------
__device__ __forceinline__ unsigned s2u(const void* p) {
    return (unsigned)__cvta_generic_to_shared(p);
}
__device__ __forceinline__ void cp16(unsigned dst, const void* src) {
    asm volatile("cp.async.cg.shared.global [%0], [%1], 16;\n" :: "r"(dst), "l"(src));
}
__device__ __forceinline__ void cp_commit() {
    asm volatile("cp.async.commit_group;\n");
}
template<int N>
__device__ __forceinline__ void cp_wait() {
    asm volatile("cp.async.wait_group %0;\n" :: "n"(N));
}
__device__ __forceinline__ unsigned cvtf(float x) {
    unsigned r;
    asm("cvt.rna.tf32.f32 %0, %1;" : "=r"(r) : "f"(x));
    return r;
}
__device__ __forceinline__ void mma8(float* c, const unsigned* a, const unsigned* b) {
    asm volatile(
        "mma.sync.aligned.m16n8k8.row.col.f32.tf32.tf32.f32 "
        "{%0,%1,%2,%3},{%4,%5,%6,%7},{%8,%9},{%0,%1,%2,%3};"
        : "+f"(c[0]), "+f"(c[1]), "+f"(c[2]), "+f"(c[3])
        : "r"(a[0]), "r"(a[1]), "r"(a[2]), "r"(a[3]), "r"(b[0]), "r"(b[1]));
}

// swizzled index inside a [rows][32] k-major tile (4-float chunk xor)
__device__ __forceinline__ int swz(int r, int k) {
    return r*32 + ((((k >> 2) ^ (r & 7)) << 2) | (k & 3));
}

// ---------------- tf32 tensor-core GEMM (3-stage cp.async) ----------------
// C(MxN) = A(MxK) @ B (+bias +res). BT=false: B is KxN. BT=true: B is NxK.
// Tile: BM = WM*32, BN = WN*32, BK = 32. Warp tile 32x32.
// grid = (M/BM, N/BN)  -- x is the M tile (fastest) so B stays hot in L2.
#define STAGES 3

template<int WM, int WN, bool BT>
__global__ __launch_bounds__(WM*WN*32) void gemm_tc(
    const float* __restrict__ A, const float* __restrict__ B,
    const float* __restrict__ bias, const float* __restrict__ res,
    float* __restrict__ C, int M, int N, int K)
{
    constexpr int BM = WM*32, BN = WN*32, NT = WM*WN*32;
    constexpr int ASZ = BM*32;                       // floats per A stage
    constexpr int BSZ = BT ? BN*32 : 32*(BN+4);      // floats per B stage

    extern __shared__ float sm[];
    float* Asm = sm;
    float* Bsm = sm + STAGES*ASZ;

    const int tid  = threadIdx.x;
    const int wid  = tid >> 5, lane = tid & 31;
    const int g    = lane >> 2, tg = lane & 3;
    const int m0   = blockIdx.x * BM, n0 = blockIdx.y * BN;
    const int wm0  = (wid / WN) * 32;
    const int wn0  = (wid % WN) * 32;

    float acc[2][4][4] = {};

    auto load_stage = [&](int t) {
        const int k0 = t * 32;
        float* As = Asm + (t % STAGES)*ASZ;
        float* Bs = Bsm + (t % STAGES)*BSZ;
        // A: BM rows x 8 chunks of 16B
        #pragma unroll
        for (int cl = tid; cl < BM*8; cl += NT) {
            int m = cl >> 3, c = cl & 7;
            unsigned dst = s2u(&As[m*32 + ((c ^ (m & 7)) << 2)]);
            cp16(dst, &A[(size_t)(m0 + m)*K + k0 + c*4]);
        }
        if (BT) {
            #pragma unroll
            for (int cl = tid; cl < BN*8; cl += NT) {
                int n = cl >> 3, c = cl & 7;
                unsigned dst = s2u(&Bs[n*32 + ((c ^ (n & 7)) << 2)]);
                cp16(dst, &B[(size_t)(n0 + n)*K + k0 + c*4]);
            }
        } else {
            #pragma unroll
            for (int cl = tid; cl < 32*(BN/4); cl += NT) {
                int kk = cl / (BN/4), c = cl % (BN/4);
                unsigned dst = s2u(&Bs[kk*(BN+4) + c*4]);
                cp16(dst, &B[(size_t)(k0 + kk)*N + n0 + c*4]);
            }
        }
        cp_commit();
    };

    auto compute = [&](int t) {
        const float* As = Asm + (t % STAGES)*ASZ;
        const float* Bs = Bsm + (t % STAGES)*BSZ;
        #pragma unroll
        for (int ks = 0; ks < 4; ks++) {
            const int k = ks*8 + tg;
            unsigned a[2][4], b[4][2];
            #pragma unroll
            for (int i = 0; i < 2; i++) {
                int m = wm0 + i*16 + g;
                a[i][0] = cvtf(As[swz(m,   k  )]);
                a[i][1] = cvtf(As[swz(m+8, k  )]);
                a[i][2] = cvtf(As[swz(m,   k+4)]);
                a[i][3] = cvtf(As[swz(m+8, k+4)]);
            }
            #pragma unroll
            for (int j = 0; j < 4; j++) {
                int n = wn0 + j*8 + g;
                if (BT) {
                    b[j][0] = cvtf(Bs[swz(n, k  )]);
                    b[j][1] = cvtf(Bs[swz(n, k+4)]);
                } else {
                    b[j][0] = cvtf(Bs[(k  )*(BN+4) + n]);
                    b[j][1] = cvtf(Bs[(k+4)*(BN+4) + n]);
                }
            }
            #pragma unroll
            for (int i = 0; i < 2; i++)
                #pragma unroll
                for (int j = 0; j < 4; j++)
                    mma8(acc[i][j], a[i], b[j]);
        }
    };

    const int NIT = K / 32;   // >= 2 at every call site
    load_stage(0);
    load_stage(1);
    for (int t = 0; t < NIT; t++) {
        if (t < NIT-1) cp_wait<1>(); else cp_wait<0>();
        __syncthreads();
        if (t + 2 < NIT) load_stage(t + 2);
        compute(t);
        __syncthreads();
    }

    // ---- epilogue ----
    #pragma unroll
    for (int i = 0; i < 2; i++) {
        int mA = m0 + wm0 + i*16 + g;
        #pragma unroll
        for (int j = 0; j < 4; j++) {
            int col = n0 + wn0 + j*8 + 2*tg;
            float b0 = bias ? bias[col] : 0.0f, b1 = bias ? bias[col+1] : 0.0f;
            float v0 = acc[i][j][0] + b0, v1 = acc[i][j][1] + b1;
            float v2 = acc[i][j][2] + b0, v3 = acc[i][j][3] + b1;
            if (res) {
                v0 += res[(size_t)mA*N + col];     v1 += res[(size_t)mA*N + col+1];
                v2 += res[(size_t)(mA+8)*N + col]; v3 += res[(size_t)(mA+8)*N + col+1];
            }
            *(float2*)&C[(size_t)mA*N + col]     = make_float2(v0, v1);
            *(float2*)&C[(size_t)(mA+8)*N + col] = make_float2(v2, v3);
        }
    }
}

// ---------------- layernorm ----------------------------------------------
__global__ __launch_bounds__(256) void ln_k(const float* __restrict__ x,
    const float* __restrict__ g, const float* __restrict__ b, float* __restrict__ y)
{
    __shared__ float sh[8];
    int s = blockIdx.x;
    int tid = threadIdx.x;
    const float* row = x + (size_t)s * D;
    float v0 = row[tid], v1 = row[tid+256], v2 = row[tid+512];
    float sum = v0 + v1 + v2;
    #pragma unroll
    for (int o = 16; o > 0; o >>= 1) sum += __shfl_xor_sync(0xffffffffu, sum, o);
    if ((tid & 31) == 0) sh[tid >> 5] = sum;
    __syncthreads();
    float tot = sh[0]+sh[1]+sh[2]+sh[3]+sh[4]+sh[5]+sh[6]+sh[7];
    float mean = tot * (1.0f/768.0f);
    float d0 = v0 - mean, d1 = v1 - mean, d2 = v2 - mean;
    float vs = d0*d0 + d1*d1 + d2*d2;
    #pragma unroll
    for (int o = 16; o > 0; o >>= 1) vs += __shfl_xor_sync(0xffffffffu, vs, o);
    __syncthreads();
    if ((tid & 31) == 0) sh[tid >> 5] = vs;
    __syncthreads();
    float var = (sh[0]+sh[1]+sh[2]+sh[3]+sh[4]+sh[5]+sh[6]+sh[7]) * (1.0f/768.0f);
    float inv = rsqrtf(var + 1e-5f);
    y[(size_t)s*D + tid      ] = d0*inv*g[tid      ] + b[tid      ];
    y[(size_t)s*D + tid + 256] = d1*inv*g[tid + 256] + b[tid + 256];
    y[(size_t)s*D + tid + 512] = d2*inv*g[tid + 512] + b[tid + 512];
}

// ---------------- position scan ------------------------------------------
__global__ void posscan_k(const float* __restrict__ h, float* __restrict__ x) {
    int d = blockIdx.x * 256 + threadIdx.x;
    if (d >= D) return;
    float acc = 0.0f;
    float c   = 0.0f;
    for (int s = 0; s < S; s++) {
        float hv = h[(size_t)s*(2*D) + d];
        float lg = h[(size_t)s*(2*D) + D + d];
        float lc = (hv >= 0.0f) ? (-log1pf(expf(-hv))) : (hv - log1pf(expf(hv)));
        acc += lc;
        float t = lg - acc;
        float mx = fmaxf(c, t), mn = fminf(c, t);
        c = mx + log1pf(expf(mn - mx));
        x[(size_t)s*D + d] += acc + c;
    }
}

// ---------------- attention pass A ---------------------------------------
__global__ __launch_bounds__(1024) void attnA_k(const float* __restrict__ qkv,
    float* __restrict__ Asum, float* __restrict__ Zsum)
{
    int c = blockIdx.x, hh = blockIdx.y;
    int tid = threadIdx.x, lane = tid & 31, wid = tid >> 5;
    __shared__ float ek[CT][33], ev[CT][33];
    const float* base = qkv + (size_t)(c*CT + wid)*QKV_N + hh*96;
    ek[wid][lane] = expf(base[32 + lane]);
    ev[wid][lane] = expf(base[64 + lane]);
    __syncthreads();
    float m = 0.0f;
    #pragma unroll
    for (int t = 0; t < CT; t++) m = fmaf(ek[t][wid], ev[t][lane], m);
    Asum[(size_t)(((hh*NCH)+c)*DKV + wid)*DKV + lane] = m;
    if (wid == 0) {
        float z = 0.0f;
        #pragma unroll
        for (int t = 0; t < CT; t++) z += ek[t][lane];
        Zsum[(size_t)((hh*NCH)+c)*DKV + lane] = z;
    }
}

// ---------------- attention pass B ---------------------------------------
__global__ __launch_bounds__(1024) void attnB_k(const float* __restrict__ Asum,
    const float* __restrict__ Zsum, float* __restrict__ Mcar, float* __restrict__ Zcar)
{
    int hh = blockIdx.x;
    int tid = threadIdx.x, lane = tid & 31, wid = tid >> 5;
    float run = 0.0f;
    for (int c = 0; c < NCH; c++) {
        size_t idx = (size_t)(((hh*NCH)+c)*DKV + wid)*DKV + lane;
        Mcar[idx] = run;
        run += Asum[idx];
    }
    if (wid == 0) {
        float rz = 0.0f;
        for (int c = 0; c < NCH; c++) {
            size_t iz = (size_t)((hh*NCH)+c)*DKV + lane;
            Zcar[iz] = rz;
            rz += Zsum[iz];
        }
    }
}

// ---------------- attention pass C ---------------------------------------
__global__ __launch_bounds__(1024) void attnC_k(const float* __restrict__ qkv,
    const float* __restrict__ Mcar, const float* __restrict__ Zcar,
    float* __restrict__ att)
{
    int c = blockIdx.x, hh = blockIdx.y;
    int tid = threadIdx.x, lane = tid & 31, wid = tid >> 5;
    __shared__ float eq[CT][33], ek[CT][33], ev[CT][33], P[CT][33], M0[DKV][33];
    __shared__ float z0[DKV];
    const float* base = qkv + (size_t)(c*CT + wid)*QKV_N + hh*96;
    eq[wid][lane] = expf(base[      lane]);
    ek[wid][lane] = expf(base[32 +  lane]);
    ev[wid][lane] = expf(base[64 +  lane]);
    M0[wid][lane] = Mcar[(size_t)(((hh*NCH)+c)*DKV + wid)*DKV + lane];
    if (tid < DKV) z0[tid] = Zcar[(size_t)((hh*NCH)+c)*DKV + tid];
    __syncthreads();
    float p = 0.0f;
    #pragma unroll
    for (int k = 0; k < DKV; k++) p = fmaf(eq[wid][k], ek[lane][k], p);
    P[wid][lane] = p;
    __syncthreads();
    float num = 0.0f, den = 0.0f;
    #pragma unroll
    for (int k = 0; k < DKV; k++) {
        float q = eq[wid][k];
        num = fmaf(q, M0[k][lane], num);
        den = fmaf(q, z0[k], den);
    }
    for (int s2 = 0; s2 <= wid; s2++) {
        float ps = P[wid][s2];
        num = fmaf(ps, ev[s2][lane], num);
        den += ps;
    }
    att[(size_t)(c*CT + wid)*D + hh*DKV + lane] = logf(num) - logf(den);
}

// ---------------- GLU ----------------------------------------------------
__global__ void glu_k(const float* __restrict__ z, float* __restrict__ o) {
    int i = blockIdx.x*256 + threadIdx.x;
    int s = i / D, d = i - s*D;
    float a = z[(size_t)s*FF_N + d];
    float g = z[(size_t)s*FF_N + D + d];
    o[i] = a * (1.0f / (1.0f + expf(-g)));
}

// ---------------- launcher -----------------------------------------------
extern "C" void kernel_launch(void* const* d_in, const int* in_sizes, int n_in,
                              void* d_out, int out_size)
{
    const int*   tok  = (const int*)  d_in[0];
    const float* embw = (const float*)d_in[1];
    const float* posw = (const float*)d_in[2];
    const float* posb = (const float*)d_in[3];
    const float* ln1g = (const float*)d_in[4];
    const float* ln1b = (const float*)d_in[5];
    const float* qkvw = (const float*)d_in[6];
    const float* qkvb = (const float*)d_in[7];
    const float* ffw1 = (const float*)d_in[8];
    const float* ffb1 = (const float*)d_in[9];
    const float* ffw2 = (const float*)d_in[10];
    const float* lnfg = (const float*)d_in[11];
    const float* lnfb = (const float*)d_in[12];
    float* out = (float*)d_out;

    float *x,*xn,*hh,*qkv,*att,*ff1,*glub,*Asum,*Zsum,*Mcar,*Zcar;
    cudaGetSymbolAddress((void**)&x,    g_x);
    cudaGetSymbolAddress((void**)&xn,   g_xn);
    cudaGetSymbolAddress((void**)&hh,   g_h);
    cudaGetSymbolAddress((void**)&qkv,  g_qkv);
    cudaGetSymbolAddress((void**)&att,  g_att);
    cudaGetSymbolAddress((void**)&ff1,  g_ff1);
    cudaGetSymbolAddress((void**)&glub, g_glu);
    cudaGetSymbolAddress((void**)&Asum, g_Asum);
    cudaGetSymbolAddress((void**)&Zsum, g_Zsum);
    cudaGetSymbolAddress((void**)&Mcar, g_Mcar);
    cudaGetSymbolAddress((void**)&Zcar, g_Zcar);

    // dynamic smem sizes (floats -> bytes): STAGES*(BM*32 + Bstage)
    const int smem_big_nn = STAGES*(128*32 + 32*(64+4))*4;  // 75264
    const int smem_sml_nn = STAGES*( 64*32 + 32*(64+4))*4;  // 50688
    const int smem_big_nt = STAGES*(128*32 + 64*32)*4;      // 73728
    cudaFuncSetAttribute(gemm_tc<4,2,false>, cudaFuncAttributeMaxDynamicSharedMemorySize, smem_big_nn);
    cudaFuncSetAttribute(gemm_tc<2,2,false>, cudaFuncAttributeMaxDynamicSharedMemorySize, smem_sml_nn);
    cudaFuncSetAttribute(gemm_tc<4,2,true >, cudaFuncAttributeMaxDynamicSharedMemorySize, smem_big_nt);

    embed_k<<<S, 256>>>(tok, embw, x);
    gemm_tc<4,2,false><<<dim3(S/128, (2*D)/64), 256, smem_big_nn>>>(
        x, posw, posb, nullptr, hh, S, 2*D, D);
    posscan_k<<<3, 256>>>(hh, x);

    for (int l = 0; l < LAYERS; l++) {
        ln_k<<<S, 256>>>(x, ln1g + (size_t)l*D, ln1b + (size_t)l*D, xn);
        gemm_tc<4,2,false><<<dim3(S/128, QKV_N/64), 256, smem_big_nn>>>(
            xn, qkvw + (size_t)l*D*QKV_N, qkvb + (size_t)l*QKV_N, nullptr, qkv, S, QKV_N, D);
        attnA_k<<<dim3(NCH, HEADS), 1024>>>(qkv, Asum, Zsum);
        attnB_k<<<HEADS, 1024>>>(Asum, Zsum, Mcar, Zcar);
        attnC_k<<<dim3(NCH, HEADS), 1024>>>(qkv, Mcar, Zcar, att);
        gemm_tc<4,2,false><<<dim3(S/128, FF_N/64), 256, smem_big_nn>>>(
            att, ffw1 + (size_t)l*D*FF_N, ffb1 + (size_t)l*FF_N, nullptr, ff1, S, FF_N, D);
        glu_k<<<(S*D)/256, 256>>>(ff1, glub);
        gemm_tc<2,2,false><<<dim3(S/64, D/64), 128, smem_sml_nn>>>(
            glub, ffw2 + (size_t)l*D*D, nullptr, x, x, S, D, D);
    }

    ln_k<<<S, 256>>>(x, lnfg, lnfb, xn);
    gemm_tc<4,2,true><<<dim3(S/128, VSZ/64), 256, smem_big_nt>>>(
        xn, embw, nullptr, nullptr, out, S, VSZ, D);
}

// round 7
// speedup vs baseline: 3.5125x; 1.4109x over previous
#include <cuda_runtime.h>
#include <cuda_fp16.h>
#include <math.h>

#define S 1024
#define D 768
#define LAYERS 12
#define HEADS 24
#define DKV 32
#define QKV_N 2304
#define FF_N 1536
#define VSZ 50304
#define NCH 32
#define CT 32

// ---------------- scratch -----------------------------------------------
__device__ float g_x[S*D];
__device__ float g_h[S*2*D];
__device__ float g_qkv[S*QKV_N];
__device__ float g_ff1[S*FF_N];
__device__ float g_Asum[HEADS*NCH*DKV*DKV];
__device__ float g_Zsum[HEADS*NCH*DKV];
__device__ float g_Mcar[HEADS*NCH*DKV*DKV];
__device__ float g_Zcar[HEADS*NCH*DKV];

__device__ __half g_xh[S*D];
__device__ __half g_xnh[S*D];
__device__ __half g_atth[S*D];
__device__ __half g_gluh[S*D];
__device__ __half g_poswh[D*2*D];
__device__ __half g_qkvwh[LAYERS*D*QKV_N];
__device__ __half g_ff1wh[LAYERS*D*FF_N];
__device__ __half g_ff2wh[LAYERS*D*D];
__device__ __half g_embwh[(size_t)VSZ*D];

// ---------------- low-level helpers --------------------------------------
__device__ __forceinline__ unsigned s2u(const void* p) {
    return (unsigned)__cvta_generic_to_shared(p);
}
__device__ __forceinline__ void cp16(unsigned dst, const void* src) {
    asm volatile("cp.async.cg.shared.global [%0], [%1], 16;\n" :: "r"(dst), "l"(src));
}
__device__ __forceinline__ void cp_commit() {
    asm volatile("cp.async.commit_group;\n");
}
template<int N>
__device__ __forceinline__ void cp_wait() {
    asm volatile("cp.async.wait_group %0;\n" :: "n"(N));
}
__device__ __forceinline__ void ldm4(unsigned* r, const __half* p) {
    unsigned a = s2u(p);
    asm volatile("ldmatrix.sync.aligned.m8n8.x4.shared.b16 {%0,%1,%2,%3}, [%4];"
        : "=r"(r[0]), "=r"(r[1]), "=r"(r[2]), "=r"(r[3]) : "r"(a));
}
__device__ __forceinline__ void mma16816(float* c, const unsigned* a, unsigned b0, unsigned b1) {
    asm volatile(
        "mma.sync.aligned.m16n8k16.row.col.f32.f16.f16.f32 "
        "{%0,%1,%2,%3},{%4,%5,%6,%7},{%8,%9},{%0,%1,%2,%3};"
        : "+f"(c[0]), "+f"(c[1]), "+f"(c[2]), "+f"(c[3])
        : "r"(a[0]), "r"(a[1]), "r"(a[2]), "r"(a[3]), "r"(b0), "r"(b1));
}
// swizzled index (half units) in a [rows][32] k-major half tile
__device__ __forceinline__ int swzh(int r, int k) {
    return r*32 + ((((k >> 3) ^ ((r >> 1) & 3)) << 3) | (k & 7));
}

// ---------------- weight prep: transpose + convert ------------------------
// src: [z][R][Cc] fp32 -> dst: [z][Cc][R] half
__global__ __launch_bounds__(256) void tconv_k(const float* __restrict__ src,
                                               __half* __restrict__ dst, int R, int Cc)
{
    __shared__ float t[32][33];
    int c0 = blockIdx.x*32, r0 = blockIdx.y*32, z = blockIdx.z;
    src += (size_t)z*R*Cc;
    dst += (size_t)z*R*Cc;
    int tx = threadIdx.x, ty = threadIdx.y;   // 32 x 8
    #pragma unroll
    for (int i = 0; i < 4; i++)
        t[ty + 8*i][tx] = src[(size_t)(r0 + ty + 8*i)*Cc + c0 + tx];
    __syncthreads();
    #pragma unroll
    for (int i = 0; i < 4; i++)
        dst[(size_t)(c0 + ty + 8*i)*R + r0 + tx] = __float2half_rn(t[tx][ty + 8*i]);
}
// straight convert fp32 -> half
__global__ __launch_bounds__(256) void conv_k(const float* __restrict__ src,
                                              __half* __restrict__ dst, size_t n2)
{
    size_t stride = (size_t)gridDim.x * blockDim.x;
    for (size_t i = (size_t)blockIdx.x*blockDim.x + threadIdx.x; i < n2; i += stride) {
        float2 v = ((const float2*)src)[i];
        ((__half2*)dst)[i] = __floats2half2_rn(v.x, v.y);
    }
}

// ---------------- embedding gather (fp32 + half) --------------------------
__global__ void embed_k(const int* __restrict__ tok, const float* __restrict__ ew,
                        float* __restrict__ x, __half* __restrict__ xh) {
    int s = blockIdx.x;
    int t = tok[s];
    for (int d = threadIdx.x; d < D; d += blockDim.x) {
        float v = ew[(size_t)t*D + d];
        x[(size_t)s*D + d] = v;
        xh[(size_t)s*D + d] = __float2half_rn(v);
    }
}

// ---------------- fp16 tensor-core GEMM (4-stage cp.async, NT only) -------
// C(MxN) fp32 = A_h(MxK) @ B_h(NxK)^T (+bias +res).
// Warp grid WGM x WGN; warp tile (SMc*16) x (SNc*16). BM=WGM*SMc*16, BN=WGN*SNc*16.
#define NSTG 4

template<int WGM, int WGN, int SMc, int SNc>
__global__ __launch_bounds__(WGM*WGN*32) void hgemm(
    const __half* __restrict__ A, const __half* __restrict__ B,
    const float* __restrict__ bias, const float* __restrict__ res,
    float* __restrict__ C, int M, int N, int K)
{
    constexpr int BM = WGM*SMc*16, BN = WGN*SNc*16, NT = WGM*WGN*32;
    constexpr int ASZ = BM*32, BSZ = BN*32;   // halfs per stage

    extern __shared__ __half sh[];
    __half* Asm = sh;
    __half* Bsm = sh + NSTG*ASZ;

    const int tid  = threadIdx.x;
    const int wid  = tid >> 5, lane = tid & 31;
    const int g    = lane >> 2, tg = lane & 3;
    const int r15  = lane & 15, khi = (lane >> 4) * 8;
    const int m0   = blockIdx.x * BM, n0 = blockIdx.y * BN;
    const int wm0  = (wid / WGN) * (SMc*16);
    const int wn0  = (wid % WGN) * (SNc*16);

    float acc[SMc][2*SNc][4] = {};

    auto load_stage = [&](int t) {
        const int k0 = t * 32;
        __half* As = Asm + (t & (NSTG-1))*ASZ;
        __half* Bs = Bsm + (t & (NSTG-1))*BSZ;
        #pragma unroll
        for (int cl = tid; cl < BM*4; cl += NT) {
            int m = cl >> 2, c = cl & 3;
            cp16(s2u(&As[m*32 + ((c ^ ((m>>1)&3)) << 3)]),
                 &A[(size_t)(m0 + m)*K + k0 + c*8]);
        }
        #pragma unroll
        for (int cl = tid; cl < BN*4; cl += NT) {
            int n = cl >> 2, c = cl & 3;
            cp16(s2u(&Bs[n*32 + ((c ^ ((n>>1)&3)) << 3)]),
                 &B[(size_t)(n0 + n)*K + k0 + c*8]);
        }
        cp_commit();
    };

    auto compute = [&](int t) {
        const __half* As = Asm + (t & (NSTG-1))*ASZ;
        const __half* Bs = Bsm + (t & (NSTG-1))*BSZ;
        #pragma unroll
        for (int kk = 0; kk < 2; kk++) {
            unsigned af[SMc][4], bf[SNc][4];
            #pragma unroll
            for (int i = 0; i < SMc; i++)
                ldm4(af[i], &As[swzh(wm0 + i*16 + r15, kk*16 + khi)]);
            #pragma unroll
            for (int j = 0; j < SNc; j++)
                ldm4(bf[j], &Bs[swzh(wn0 + j*16 + r15, kk*16 + khi)]);
            #pragma unroll
            for (int i = 0; i < SMc; i++)
                #pragma unroll
                for (int j = 0; j < SNc; j++) {
                    mma16816(acc[i][2*j  ], af[i], bf[j][0], bf[j][2]);
                    mma16816(acc[i][2*j+1], af[i], bf[j][1], bf[j][3]);
                }
        }
    };

    const int NIT = K / 32;    // 24 at every call site
    load_stage(0); load_stage(1); load_stage(2);
    for (int t = 0; t < NIT; t++) {
        if (t < NIT-2)       cp_wait<2>();
        else if (t == NIT-2) cp_wait<1>();
        else                 cp_wait<0>();
        __syncthreads();
        if (t + 3 < NIT) load_stage(t + 3);
        compute(t);
        __syncthreads();
    }

    // ---- epilogue (fp32) ----
    #pragma unroll
    for (int i = 0; i < SMc; i++) {
        int mA = m0 + wm0 + i*16 + g;
        #pragma unroll
        for (int jj = 0; jj < 2*SNc; jj++) {
            int col = n0 + wn0 + (jj >> 1)*16 + (jj & 1)*8 + 2*tg;
            float b0 = bias ? bias[col] : 0.0f, b1 = bias ? bias[col+1] : 0.0f;
            float v0 = acc[i][jj][0] + b0, v1 = acc[i][jj][1] + b1;
            float v2 = acc[i][jj][2] + b0, v3 = acc[i][jj][3] + b1;
            if (res) {
                v0 += res[(size_t)mA*N + col];     v1 += res[(size_t)mA*N + col+1];
                v2 += res[(size_t)(mA+8)*N + col]; v3 += res[(size_t)(mA+8)*N + col+1];
            }
            *(float2*)&C[(size_t)mA*N + col]     = make_float2(v0, v1);
            *(float2*)&C[(size_t)(mA+8)*N + col] = make_float2(v2, v3);
        }
    }
}

// ---------------- layernorm (fp32 in -> half out) --------------------------
__global__ __launch_bounds__(256) void ln_k(const float* __restrict__ x,
    const float* __restrict__ g, const float* __restrict__ b, __half* __restrict__ y)
{
    __shared__ float sh[8];
    int s = blockIdx.x;
    int tid = threadIdx.x;
    const float* row = x + (size_t)s * D;
    float v0 = row[tid], v1 = row[tid+256], v2 = row[tid+512];
    float sum = v0 + v1 + v2;
    #pragma unroll
    for (int o = 16; o > 0; o >>= 1) sum += __shfl_xor_sync(0xffffffffu, sum, o);
    if ((tid & 31) == 0) sh[tid >> 5] = sum;
    __syncthreads();
    float tot = sh[0]+sh[1]+sh[2]+sh[3]+sh[4]+sh[5]+sh[6]+sh[7];
    float mean = tot * (1.0f/768.0f);
    float d0 = v0 - mean, d1 = v1 - mean, d2 = v2 - mean;
    float vs = d0*d0 + d1*d1 + d2*d2;
    #pragma unroll
    for (int o = 16; o > 0; o >>= 1) vs += __shfl_xor_sync(0xffffffffu, vs, o);
    __syncthreads();
    if ((tid & 31) == 0) sh[tid >> 5] = vs;
    __syncthreads();
    float var = (sh[0]+sh[1]+sh[2]+sh[3]+sh[4]+sh[5]+sh[6]+sh[7]) * (1.0f/768.0f);
    float inv = rsqrtf(var + 1e-5f);
    y[(size_t)s*D + tid      ] = __float2half_rn(d0*inv*g[tid      ] + b[tid      ]);
    y[(size_t)s*D + tid + 256] = __float2half_rn(d1*inv*g[tid + 256] + b[tid + 256]);
    y[(size_t)s*D + tid + 512] = __float2half_rn(d2*inv*g[tid + 512] + b[tid + 512]);
}

// ---------------- position scan ------------------------------------------
__global__ void posscan_k(const float* __restrict__ h, float* __restrict__ x) {
    int d = blockIdx.x * 256 + threadIdx.x;
    if (d >= D) return;
    float acc = 0.0f;
    float c   = 0.0f;
    for (int s = 0; s < S; s++) {
        float hv = h[(size_t)s*(2*D) + d];
        float lg = h[(size_t)s*(2*D) + D + d];
        float lc = (hv >= 0.0f) ? (-log1pf(expf(-hv))) : (hv - log1pf(expf(hv)));
        acc += lc;
        float t = lg - acc;
        float mx = fmaxf(c, t), mn = fminf(c, t);
        c = mx + log1pf(expf(mn - mx));
        x[(size_t)s*D + d] += acc + c;
    }
}

// ---------------- attention pass A ---------------------------------------
__global__ __launch_bounds__(1024) void attnA_k(const float* __restrict__ qkv,
    float* __restrict__ Asum, float* __restrict__ Zsum)
{
    int c = blockIdx.x, hh = blockIdx.y;
    int tid = threadIdx.x, lane = tid & 31, wid = tid >> 5;
    __shared__ float ek[CT][33], ev[CT][33];
    const float* base = qkv + (size_t)(c*CT + wid)*QKV_N + hh*96;
    ek[wid][lane] = expf(base[32 + lane]);
    ev[wid][lane] = expf(base[64 + lane]);
    __syncthreads();
    float m = 0.0f;
    #pragma unroll
    for (int t = 0; t < CT; t++) m = fmaf(ek[t][wid], ev[t][lane], m);
    Asum[(size_t)(((hh*NCH)+c)*DKV + wid)*DKV + lane] = m;
    if (wid == 0) {
        float z = 0.0f;
        #pragma unroll
        for (int t = 0; t < CT; t++) z += ek[t][lane];
        Zsum[(size_t)((hh*NCH)+c)*DKV + lane] = z;
    }
}

// ---------------- attention pass B ---------------------------------------
__global__ __launch_bounds__(1024) void attnB_k(const float* __restrict__ Asum,
    const float* __restrict__ Zsum, float* __restrict__ Mcar, float* __restrict__ Zcar)
{
    int hh = blockIdx.x;
    int tid = threadIdx.x, lane = tid & 31, wid = tid >> 5;
    float run = 0.0f;
    for (int c = 0; c < NCH; c++) {
        size_t idx = (size_t)(((hh*NCH)+c)*DKV + wid)*DKV + lane;
        Mcar[idx] = run;
        run += Asum[idx];
    }
    if (wid == 0) {
        float rz = 0.0f;
        for (int c = 0; c < NCH; c++) {
            size_t iz = (size_t)((hh*NCH)+c)*DKV + lane;
            Zcar[iz] = rz;
            rz += Zsum[iz];
        }
    }
}

// ---------------- attention pass C (half out) -----------------------------
__global__ __launch_bounds__(1024) void attnC_k(const float* __restrict__ qkv,
    const float* __restrict__ Mcar, const float* __restrict__ Zcar,
    __half* __restrict__ att)
{
    int c = blockIdx.x, hh = blockIdx.y;
    int tid = threadIdx.x, lane = tid & 31, wid = tid >> 5;
    __shared__ float eq[CT][33], ek[CT][33], ev[CT][33], P[CT][33], M0[DKV][33];
    __shared__ float z0[DKV];
    const float* base = qkv + (size_t)(c*CT + wid)*QKV_N + hh*96;
    eq[wid][lane] = expf(base[      lane]);
    ek[wid][lane] = expf(base[32 +  lane]);
    ev[wid][lane] = expf(base[64 +  lane]);
    M0[wid][lane] = Mcar[(size_t)(((hh*NCH)+c)*DKV + wid)*DKV + lane];
    if (tid < DKV) z0[tid] = Zcar[(size_t)((hh*NCH)+c)*DKV + tid];
    __syncthreads();
    float p = 0.0f;
    #pragma unroll
    for (int k = 0; k < DKV; k++) p = fmaf(eq[wid][k], ek[lane][k], p);
    P[wid][lane] = p;
    __syncthreads();
    float num = 0.0f, den = 0.0f;
    #pragma unroll
    for (int k = 0; k < DKV; k++) {
        float q = eq[wid][k];
        num = fmaf(q, M0[k][lane], num);
        den = fmaf(q, z0[k], den);
    }
    for (int s2 = 0; s2 <= wid; s2++) {
        float ps = P[wid][s2];
        num = fmaf(ps, ev[s2][lane], num);
        den += ps;
    }
    att[(size_t)(c*CT + wid)*D + hh*DKV + lane] = __float2half_rn(logf(num) - logf(den));
}

// ---------------- GLU (half out) ------------------------------------------
__global__ void glu_k(const float* __restrict__ z, __half* __restrict__ o) {
    int i = blockIdx.x*256 + threadIdx.x;
    int s = i / D, d = i - s*D;
    float a = z[(size_t)s*FF_N + d];
    float g = z[(size_t)s*FF_N + D + d];
    o[i] = __float2half_rn(a * (1.0f / (1.0f + expf(-g))));
}

// ---------------- launcher -----------------------------------------------
extern "C" void kernel_launch(void* const* d_in, const int* in_sizes, int n_in,
                              void* d_out, int out_size)
{
    const int*   tok  = (const int*)  d_in[0];
    const float* embw = (const float*)d_in[1];
    const float* posw = (const float*)d_in[2];
    const float* posb = (const float*)d_in[3];
    const float* ln1g = (const float*)d_in[4];
    const float* ln1b = (const float*)d_in[5];
    const float* qkvw = (const float*)d_in[6];
    const float* qkvb = (const float*)d_in[7];
    const float* ffw1 = (const float*)d_in[8];
    const float* ffb1 = (const float*)d_in[9];
    const float* ffw2 = (const float*)d_in[10];
    const float* lnfg = (const float*)d_in[11];
    const float* lnfb = (const float*)d_in[12];
    float* out = (float*)d_out;

    float *x,*hh,*qkv,*ff1,*Asum,*Zsum,*Mcar,*Zcar;
    __half *xh,*xnh,*atth,*gluh,*poswh,*qkvwh,*ff1wh,*ff2wh,*embwh;
    cudaGetSymbolAddress((void**)&x,    g_x);
    cudaGetSymbolAddress((void**)&hh,   g_h);
    cudaGetSymbolAddress((void**)&qkv,  g_qkv);
    cudaGetSymbolAddress((void**)&ff1,  g_ff1);
    cudaGetSymbolAddress((void**)&Asum, g_Asum);
    cudaGetSymbolAddress((void**)&Zsum, g_Zsum);
    cudaGetSymbolAddress((void**)&Mcar, g_Mcar);
    cudaGetSymbolAddress((void**)&Zcar, g_Zcar);
    cudaGetSymbolAddress((void**)&xh,    g_xh);
    cudaGetSymbolAddress((void**)&xnh,   g_xnh);
    cudaGetSymbolAddress((void**)&atth,  g_atth);
    cudaGetSymbolAddress((void**)&gluh,  g_gluh);
    cudaGetSymbolAddress((void**)&poswh, g_poswh);
    cudaGetSymbolAddress((void**)&qkvwh, g_qkvwh);
    cudaGetSymbolAddress((void**)&ff1wh, g_ff1wh);
    cudaGetSymbolAddress((void**)&ff2wh, g_ff2wh);
    cudaGetSymbolAddress((void**)&embwh, g_embwh);

    // smem per config: NSTG*(BM+BN)*32 halfs
    const int sm_P = NSTG*( 64+128)*32*2;   // 49152  (64x128)
    const int sm_S = NSTG*( 64+ 64)*32*2;   // 32768  (64x64)
    const int sm_L = NSTG*(128+128)*32*2;   // 65536  (128x128)
    cudaFuncSetAttribute(hgemm<2,4,2,2>, cudaFuncAttributeMaxDynamicSharedMemorySize, sm_P);
    cudaFuncSetAttribute(hgemm<2,2,2,2>, cudaFuncAttributeMaxDynamicSharedMemorySize, sm_S);
    cudaFuncSetAttribute(hgemm<2,4,4,2>, cudaFuncAttributeMaxDynamicSharedMemorySize, sm_L);

    // ---- weight prep (every call; deterministic) ----
    tconv_k<<<dim3(2*D/32,  D/32, 1     ), dim3(32,8)>>>(posw, poswh, D, 2*D);
    tconv_k<<<dim3(QKV_N/32,D/32, LAYERS), dim3(32,8)>>>(qkvw, qkvwh, D, QKV_N);
    tconv_k<<<dim3(FF_N/32, D/32, LAYERS), dim3(32,8)>>>(ffw1, ff1wh, D, FF_N);
    tconv_k<<<dim3(D/32,    D/32, LAYERS), dim3(32,8)>>>(ffw2, ff2wh, D, D);
    conv_k<<<1024, 256>>>(embw, embwh, (size_t)VSZ*D/2);

    // ---- embed + position recurrence ----
    embed_k<<<S, 256>>>(tok, embw, x, xh);
    hgemm<2,4,2,2><<<dim3(S/64, 2*D/128), 256, sm_P>>>(
        xh, poswh, posb, nullptr, hh, S, 2*D, D);
    posscan_k<<<3, 256>>>(hh, x);

    for (int l = 0; l < LAYERS; l++) {
        ln_k<<<S, 256>>>(x, ln1g + (size_t)l*D, ln1b + (size_t)l*D, xnh);
        hgemm<2,4,2,2><<<dim3(S/64, QKV_N/128), 256, sm_P>>>(
            xnh, qkvwh + (size_t)l*D*QKV_N, qkvb + (size_t)l*QKV_N, nullptr, qkv, S, QKV_N, D);
        attnA_k<<<dim3(NCH, HEADS), 1024>>>(qkv, Asum, Zsum);
        attnB_k<<<HEADS, 1024>>>(Asum, Zsum, Mcar, Zcar);
        attnC_k<<<dim3(NCH, HEADS), 1024>>>(qkv, Mcar, Zcar, atth);
        hgemm<2,4,2,2><<<dim3(S/64, FF_N/128), 256, sm_P>>>(
            atth, ff1wh + (size_t)l*D*FF_N, ffb1 + (size_t)l*FF_N, nullptr, ff1, S, FF_N, D);
        glu_k<<<(S*D)/256, 256>>>(ff1, gluh);
        hgemm<2,2,2,2><<<dim3(S/64, D/64), 128, sm_S>>>(
            gluh, ff2wh + (size_t)l*D*D, nullptr, x, x, S, D, D);
    }

    ln_k<<<S, 256>>>(x, lnfg, lnfb, xnh);
    hgemm<2,4,4,2><<<dim3(S/128, VSZ/128), 256, sm_L>>>(
        xnh, embwh, nullptr, nullptr, out, S, VSZ, D);
}